// round 16
// baseline (speedup 1.0000x reference)
#include <cuda_runtime.h>
#include <cuda_bf16.h>
#include <mma.h>
#include <cstdint>

namespace wm = nvcuda::wmma;

#define NN 20000
#define EE 160000
#define FIN 9
#define F 64
#define NL 7
#define DIM 3
#define BN_EPS 1e-5f
#define NT_T128 1250
#define ND_TILES 313

typedef unsigned long long ull;
union F4U { float4 v; ull u[2]; float f[4]; };

// ---------------- device scratch ----------------
__device__ float d_h[NN * F];
__device__ __nv_bfloat16 d_hhi[NN * F];
__device__ __nv_bfloat16 d_hlo[NN * F];
__device__ float d_pos[NN * DIM];
__device__ __nv_bfloat16 d_m1hi[EE * F];
__device__ __nv_bfloat16 d_m1lo[EE * F];
__device__ float d_dvec[EE * DIM];
__device__ float d_summ1[NN * F];
__device__ float d_aggpm[NN * DIM];
__device__ int   d_counts[NN];
__device__ float d_invc[NN];
__device__ float d_bnsum[NL * F];
__device__ float d_bnsumsq[NL * F];
__device__ __nv_bfloat16 d_w1hi[NL * F * 128];   // [l][j][k]
__device__ __nv_bfloat16 d_w1lo[NL * F * 128];
__device__ volatile unsigned d_bar;

__device__ __forceinline__ float silu_f(float x) { return x / (1.0f + expf(-x)); }

__device__ __forceinline__ ull ffma2(ull a, ull b, ull c) {
    ull d;
    asm("fma.rn.f32x2 %0, %1, %2, %3;" : "=l"(d) : "l"(a), "l"(b), "l"(c));
    return d;
}
__device__ __forceinline__ float lane_sum(ull a) {
    float lo = __uint_as_float((unsigned)(a & 0xffffffffull));
    float hi = __uint_as_float((unsigned)(a >> 32));
    return lo + hi;
}
__device__ __forceinline__ void red_add_v4(float* p, float a, float b, float c, float d) {
    asm volatile("red.global.add.v4.f32 [%0], {%1,%2,%3,%4};"
                 :: "l"(p), "f"(a), "f"(b), "f"(c), "f"(d) : "memory");
}
__device__ __forceinline__ unsigned pack_bf(__nv_bfloat16 a, __nv_bfloat16 b) {
    __nv_bfloat162 t(a, b); return *(unsigned*)&t;
}
__device__ __forceinline__ void grid_barrier(unsigned target) {
    __threadfence();
    __syncthreads();
    if (threadIdx.x == 0) {
        atomicAdd((unsigned*)&d_bar, 1u);
        while (d_bar < target) { __nanosleep(64); }
    }
    __syncthreads();
    __threadfence();
}

// ---------------- FFMA2 GEMM core ----------------
template<int PF, int PW>
__device__ __forceinline__ void gemm_acc4(const float* __restrict__ sf,
                                          const float* __restrict__ sWt,
                                          int kmax, int et, int jt, ull acc[4][4]) {
    const float* fb = sf + et * PF;
    const float* wb = sWt + (jt * 4) * PW;
    #pragma unroll 2
    for (int k0 = 0; k0 < kmax; k0 += 4) {
        ull w[4][2];
        #pragma unroll
        for (int j = 0; j < 4; ++j) {
            F4U t; t.v = *(const float4*)(wb + j * PW + k0);
            w[j][0] = t.u[0]; w[j][1] = t.u[1];
        }
        #pragma unroll
        for (int e = 0; e < 4; ++e) {
            F4U t; t.v = *(const float4*)(fb + e * 16 * PF + k0);
            #pragma unroll
            for (int j = 0; j < 4; ++j) {
                acc[e][j] = ffma2(t.u[0], w[j][0], acc[e][j]);
                acc[e][j] = ffma2(t.u[1], w[j][1], acc[e][j]);
            }
        }
    }
}

// ---------------- init ----------------
__global__ void init_kernel(const float* __restrict__ pos_in) {
    int i = blockIdx.x * blockDim.x + threadIdx.x;
    if (i < NN * F) d_summ1[i] = 0.0f;
    if (i < NN * DIM) { d_aggpm[i] = 0.0f; d_pos[i] = pos_in[i]; }
    if (i < NN) d_counts[i] = 0;
    if (i < NL * F) { d_bnsum[i] = 0.0f; d_bnsumsq[i] = 0.0f; }
    if (i == 0) d_bar = 0;
}
__global__ void count_kernel(const int* __restrict__ edge_dst) {
    int i = blockIdx.x * blockDim.x + threadIdx.x;
    if (i < EE) atomicAdd(&d_counts[edge_dst[i]], 1);
}
__global__ void inv_kernel() {
    int i = blockIdx.x * blockDim.x + threadIdx.x;
    if (i < NN) d_invc[i] = 1.0f / fmaxf((float)d_counts[i], 1.0f);
}
__global__ void wconv_kernel(const float* __restrict__ msg_W1) {
    int idx = blockIdx.x * blockDim.x + threadIdx.x;
    if (idx >= NL * F * 128) return;
    int l = idx >> 13, r = idx & 8191;
    int j = r >> 7, k = r & 127;
    float v = msg_W1[l * 8256 + k * 64 + j];
    __nv_bfloat16 h = __float2bfloat16(v);
    d_w1hi[idx] = h;
    d_w1lo[idx] = __float2bfloat16(v - __bfloat162float(h));
}

// ---------------- embedding (FFMA2) + h hi/lo emission ----------------
#define EM_SMEM ((64*12 + 64*12 + 64*68 + 64*68 + 128) * (int)sizeof(float))
__global__ void embed_kernel(const float* __restrict__ h_in,
                             const float* __restrict__ W1, const float* __restrict__ b1,
                             const float* __restrict__ W2, const float* __restrict__ b2) {
    extern __shared__ float sm[];
    float* sf   = sm;
    float* sW1t = sf + 64 * 12;
    float* sfB  = sW1t + 64 * 12;
    float* sW2t = sfB + 64 * 68;
    float* sb1  = sW2t + 64 * 68;
    float* sb2  = sb1 + 64;
    int tid = threadIdx.x;
    int base = blockIdx.x * 64;
    for (int idx = tid; idx < 64 * 12; idx += 256) {
        int j = idx / 12, k = idx - j * 12;
        sW1t[idx] = (k < FIN) ? W1[k * 64 + j] : 0.0f;
    }
    for (int idx = tid; idx < 64 * 64; idx += 256) {
        int k = idx >> 6, j = idx & 63;
        sW2t[j * 68 + k] = W2[idx];
    }
    if (tid < 64) { sb1[tid] = b1[tid]; sb2[tid] = b2[tid]; }
    for (int idx = tid; idx < 64 * 12; idx += 256) {
        int e = idx / 12, k = idx - e * 12;
        int n = base + e;
        sf[idx] = (k < FIN && n < NN) ? h_in[n * FIN + k] : 0.0f;
    }
    __syncthreads();
    int et = tid & 15, jt = tid >> 4;
    {
        ull acc[4][4] = {};
        gemm_acc4<12, 12>(sf, sW1t, 12, et, jt, acc);
        #pragma unroll
        for (int e = 0; e < 4; ++e) {
            F4U o;
            #pragma unroll
            for (int j = 0; j < 4; ++j)
                o.f[j] = silu_f(lane_sum(acc[e][j]) + sb1[jt * 4 + j]);
            *(float4*)(sfB + (et + 16 * e) * 68 + jt * 4) = o.v;
        }
    }
    __syncthreads();
    {
        ull acc[4][4] = {};
        gemm_acc4<68, 68>(sfB, sW2t, 64, et, jt, acc);
        #pragma unroll
        for (int e = 0; e < 4; ++e) {
            int n = base + et + 16 * e;
            if (n < NN) {
                F4U o;
                #pragma unroll
                for (int j = 0; j < 4; ++j)
                    o.f[j] = lane_sum(acc[e][j]) + sb2[jt * 4 + j];
                *(float4*)(d_h + n * 64 + jt * 4) = o.v;
                __nv_bfloat16 hb[4]; float lo[4];
                #pragma unroll
                for (int j = 0; j < 4; ++j) {
                    hb[j] = __float2bfloat16(o.f[j]);
                    lo[j] = o.f[j] - __bfloat162float(hb[j]);
                }
                uint2 H, L;
                H.x = pack_bf(hb[0], hb[1]); H.y = pack_bf(hb[2], hb[3]);
                L.x = pack_bf(__float2bfloat16(lo[0]), __float2bfloat16(lo[1]));
                L.y = pack_bf(__float2bfloat16(lo[2]), __float2bfloat16(lo[3]));
                *(uint2*)(d_hhi + n * 64 + jt * 4) = H;
                *(uint2*)(d_hlo + n * 64 + jt * 4) = L;
            }
        }
    }
}

// ---------------- fused layer kernel: pass1 | barrier | pass2 | barrier | node ----------------
#define LY_SMEM 106496
__global__ void __launch_bounds__(256, 2)
layer_kernel(const int* __restrict__ esrc, const int* __restrict__ edst,
             const float* __restrict__ cell,
             const float* __restrict__ W1, const float* __restrict__ b1,
             const float* __restrict__ gamma, const float* __restrict__ beta,
             const float* __restrict__ W2, const float* __restrict__ b2,
             const float* __restrict__ pW1, const float* __restrict__ pb1,
             const float* __restrict__ pW2, const float* __restrict__ pb2,
             const float* __restrict__ uW1, const float* __restrict__ ub1,
             const float* __restrict__ uW2, const float* __restrict__ ub2,
             const float* __restrict__ uW3, const float* __restrict__ ub3, int l) {
    extern __shared__ char smem[];
    int tid = threadIdx.x;
    int w = tid >> 5, rg = w >> 1, nh = w & 1;
    int et = tid & 15, jt = tid >> 4;

    // ================= phase 1: pass1 (wmma + fused BN stats) =================
    {
        __nv_bfloat16* sAhi = (__nv_bfloat16*)(smem);
        __nv_bfloat16* sAlo = (__nv_bfloat16*)(smem + 34816);
        __nv_bfloat16* sBhi = (__nv_bfloat16*)(smem + 69632);
        __nv_bfloat16* sBlo = (__nv_bfloat16*)(smem + 87040);
        float* sAcc  = (float*)(smem);
        float* w129  = (float*)(smem + 104448);
        float* sb1   = (float*)(smem + 104704);
        float* sdist = (float*)(smem + 104960);
        int*   sdst  = (int*)(smem + 105472);
        int*   ssrc  = (int*)(smem + 105984);
        for (int i = tid; i < 64 * 16; i += 256) {
            int j = i >> 4, c = i & 15;
            *(uint4*)(sBhi + j * 136 + c * 8) = ((const uint4*)(d_w1hi + l * 8192 + j * 128))[c];
            *(uint4*)(sBlo + j * 136 + c * 8) = ((const uint4*)(d_w1lo + l * 8192 + j * 128))[c];
        }
        if (tid < 64) { w129[tid] = W1[128 * 64 + tid]; sb1[tid] = b1[tid]; }
        int cb = tid >> 5, el = tid & 31, j0 = cb * 8;
        float lsum[8] = {0,0,0,0,0,0,0,0}, lsq[8] = {0,0,0,0,0,0,0,0};

        for (int t = blockIdx.x; t < NT_T128; t += gridDim.x) {
            int base = t * 128;
            __syncthreads();
            if (tid < 128) {
                int ge = base + tid;
                int dn = edst[ge], sn = esrc[ge];
                sdst[tid] = dn; ssrc[tid] = sn;
                float dv0 = d_pos[dn * 3 + 0] - d_pos[sn * 3 + 0] + cell[ge * 3 + 0];
                float dv1 = d_pos[dn * 3 + 1] - d_pos[sn * 3 + 1] + cell[ge * 3 + 1];
                float dv2 = d_pos[dn * 3 + 2] - d_pos[sn * 3 + 2] + cell[ge * 3 + 2];
                d_dvec[ge * 3 + 0] = dv0; d_dvec[ge * 3 + 1] = dv1; d_dvec[ge * 3 + 2] = dv2;
                sdist[tid] = dv0 + dv1 + dv2;
            }
            __syncthreads();
            for (int idx = tid; idx < 128 * 32; idx += 256) {
                int e = idx >> 5, q = idx & 31, c = q & 7;
                int n = (q & 8) ? ssrc[e] : sdst[e];
                const uint4* src = (q & 16) ? (const uint4*)(d_hlo + n * 64)
                                            : (const uint4*)(d_hhi + n * 64);
                __nv_bfloat16* dp = ((q & 16) ? sAlo : sAhi) + e * 136 + ((q & 8) ? 64 : 0) + c * 8;
                *(uint4*)dp = src[c];
            }
            __syncthreads();
            wm::fragment<wm::accumulator, 16, 16, 16, float> c00, c01, c10, c11;
            wm::fill_fragment(c00, 0.0f); wm::fill_fragment(c01, 0.0f);
            wm::fill_fragment(c10, 0.0f); wm::fill_fragment(c11, 0.0f);
            {
                const __nv_bfloat16* Ah = sAhi + rg * 32 * 136;
                const __nv_bfloat16* Al = sAlo + rg * 32 * 136;
                const __nv_bfloat16* B0h = sBhi + (nh * 32) * 136;
                const __nv_bfloat16* B1h = sBhi + (nh * 32 + 16) * 136;
                const __nv_bfloat16* B0l = sBlo + (nh * 32) * 136;
                const __nv_bfloat16* B1l = sBlo + (nh * 32 + 16) * 136;
                #pragma unroll
                for (int kt = 0; kt < 8; ++kt) {
                    wm::fragment<wm::matrix_a, 16, 16, 16, __nv_bfloat16, wm::row_major> ah0, ah1, al0, al1;
                    wm::load_matrix_sync(ah0, Ah + kt * 16, 136);
                    wm::load_matrix_sync(ah1, Ah + 16 * 136 + kt * 16, 136);
                    wm::load_matrix_sync(al0, Al + kt * 16, 136);
                    wm::load_matrix_sync(al1, Al + 16 * 136 + kt * 16, 136);
                    wm::fragment<wm::matrix_b, 16, 16, 16, __nv_bfloat16, wm::col_major> b;
                    wm::load_matrix_sync(b, B0h + kt * 16, 136);
                    wm::mma_sync(c00, ah0, b, c00);
                    wm::mma_sync(c10, ah1, b, c10);
                    wm::mma_sync(c00, al0, b, c00);
                    wm::mma_sync(c10, al1, b, c10);
                    wm::load_matrix_sync(b, B1h + kt * 16, 136);
                    wm::mma_sync(c01, ah0, b, c01);
                    wm::mma_sync(c11, ah1, b, c11);
                    wm::mma_sync(c01, al0, b, c01);
                    wm::mma_sync(c11, al1, b, c11);
                    wm::load_matrix_sync(b, B0l + kt * 16, 136);
                    wm::mma_sync(c00, ah0, b, c00);
                    wm::mma_sync(c10, ah1, b, c10);
                    wm::load_matrix_sync(b, B1l + kt * 16, 136);
                    wm::mma_sync(c01, ah0, b, c01);
                    wm::mma_sync(c11, ah1, b, c11);
                }
            }
            __syncthreads();
            wm::store_matrix_sync(sAcc + (rg * 32) * 68 + nh * 32, c00, 68, wm::mem_row_major);
            wm::store_matrix_sync(sAcc + (rg * 32) * 68 + nh * 32 + 16, c01, 68, wm::mem_row_major);
            wm::store_matrix_sync(sAcc + (rg * 32 + 16) * 68 + nh * 32, c10, 68, wm::mem_row_major);
            wm::store_matrix_sync(sAcc + (rg * 32 + 16) * 68 + nh * 32 + 16, c11, 68, wm::mem_row_major);
            __syncthreads();
            #pragma unroll
            for (int i = 0; i < 4; ++i) {
                int e = el + 32 * i;
                int ge = base + e;
                int dn = sdst[e];
                float dist = sdist[e];
                float mv[8];
                __nv_bfloat16 hb[8], lb[8];
                #pragma unroll
                for (int jj = 0; jj < 8; ++jj) {
                    int j = j0 + jj;
                    float v = sAcc[e * 68 + j] + dist * w129[j] + sb1[j];
                    v = silu_f(v);
                    mv[jj] = v;
                    lsum[jj] += v; lsq[jj] += v * v;
                    hb[jj] = __float2bfloat16(v);
                    lb[jj] = __float2bfloat16(v - __bfloat162float(hb[jj]));
                }
                uint4 H, L;
                H.x = pack_bf(hb[0], hb[1]); H.y = pack_bf(hb[2], hb[3]);
                H.z = pack_bf(hb[4], hb[5]); H.w = pack_bf(hb[6], hb[7]);
                L.x = pack_bf(lb[0], lb[1]); L.y = pack_bf(lb[2], lb[3]);
                L.z = pack_bf(lb[4], lb[5]); L.w = pack_bf(lb[6], lb[7]);
                ((uint4*)(d_m1hi + (size_t)ge * 64))[cb] = H;
                ((uint4*)(d_m1lo + (size_t)ge * 64))[cb] = L;
                red_add_v4(d_summ1 + dn * 64 + j0,     mv[0], mv[1], mv[2], mv[3]);
                red_add_v4(d_summ1 + dn * 64 + j0 + 4, mv[4], mv[5], mv[6], mv[7]);
            }
        }
        #pragma unroll
        for (int jj = 0; jj < 8; ++jj) {
            #pragma unroll
            for (int o = 1; o < 32; o <<= 1) {
                lsum[jj] += __shfl_xor_sync(0xffffffffu, lsum[jj], o);
                lsq[jj]  += __shfl_xor_sync(0xffffffffu, lsq[jj], o);
            }
        }
        if (el == 0) {
            #pragma unroll
            for (int jj = 0; jj < 8; ++jj) {
                atomicAdd(&d_bnsum[l * 64 + j0 + jj], lsum[jj]);
                atomicAdd(&d_bnsumsq[l * 64 + j0 + jj], lsq[jj]);
            }
        }
    }
    grid_barrier((3u * l + 1u) * gridDim.x);

    // ================= phase 2: pass2 (BN prep + wmma + pm scatter) =================
    {
        __nv_bfloat16* sAhi = (__nv_bfloat16*)(smem);
        __nv_bfloat16* sAlo = (__nv_bfloat16*)(smem + 18432);
        __nv_bfloat16* sBhi = (__nv_bfloat16*)(smem + 36864);
        __nv_bfloat16* sBlo = (__nv_bfloat16*)(smem + 46080);
        float* sAcc = (float*)(smem);
        float* sW2f = (float*)(smem);
        float* spW1f = (float*)(smem + 18432);
        float* sbc  = (float*)(smem + 55296);
        float* spW2 = (float*)(smem + 55552);
        float* spb2 = (float*)(smem + 56320);
        float* sdv  = (float*)(smem + 56336);
        int*   sdst = (int*)(smem + 57872);
        float* sA   = (float*)(smem + 58384);
        float* sB   = (float*)(smem + 58640);
        float* sv   = (float*)(smem + 58896);
        for (int idx = tid; idx < 4096; idx += 256) {
            sW2f[idx] = W2[idx];
            spW1f[idx] = pW1[idx];
        }
        for (int i = tid; i < 192; i += 256) spW2[i] = pW2[i];
        if (tid < 3) spb2[tid] = pb2[tid];
        if (tid < 64) {
            float mu  = d_bnsum[l * 64 + tid]   * (1.0f / (float)EE);
            float var = d_bnsumsq[l * 64 + tid] * (1.0f / (float)EE) - mu * mu;
            float inv = rsqrtf(var + BN_EPS);
            float A = gamma[tid] * inv;
            sA[tid] = A;
            sB[tid] = beta[tid] - mu * A;
        }
        __syncthreads();
        if (tid < 64) {
            float acc = b2[tid];
            #pragma unroll 8
            for (int k = 0; k < 64; ++k) acc += sB[k] * sW2f[k * 64 + tid];
            sv[tid] = acc;
        }
        __syncthreads();
        if (tid < 64) {
            float acc = pb1[tid];
            #pragma unroll 8
            for (int q = 0; q < 64; ++q) acc += sv[q] * spW1f[q * 64 + tid];
            sbc[tid] = acc;
        }
        for (int idx = tid; idx < 4096; idx += 256) {
            int k = idx >> 6, j = idx & 63;
            float acc = 0.0f;
            #pragma unroll 8
            for (int q = 0; q < 64; ++q) acc += sW2f[k * 64 + q] * spW1f[q * 64 + j];
            float v = sA[k] * acc;
            __nv_bfloat16 h = __float2bfloat16(v);
            sBhi[j * 72 + k] = h;
            sBlo[j * 72 + k] = __float2bfloat16(v - __bfloat162float(h));
        }
        for (int t = blockIdx.x; t < NT_T128; t += gridDim.x) {
            int base = t * 128;
            __syncthreads();
            if (tid < 128) sdst[tid] = edst[base + tid];
            for (int i = tid; i < 384; i += 256) sdv[i] = d_dvec[base * 3 + i];
            for (int idx = tid; idx < 128 * 16; idx += 256) {
                int e = idx >> 4, q = idx & 15, c = q & 7;
                const uint4* src = (q & 8) ? (const uint4*)(d_m1lo + (size_t)(base + e) * 64)
                                           : (const uint4*)(d_m1hi + (size_t)(base + e) * 64);
                __nv_bfloat16* dp = ((q & 8) ? sAlo : sAhi) + e * 72 + c * 8;
                *(uint4*)dp = src[c];
            }
            __syncthreads();
            wm::fragment<wm::accumulator, 16, 16, 16, float> c00, c01, c10, c11;
            wm::fill_fragment(c00, 0.0f); wm::fill_fragment(c01, 0.0f);
            wm::fill_fragment(c10, 0.0f); wm::fill_fragment(c11, 0.0f);
            {
                const __nv_bfloat16* Ah = sAhi + rg * 32 * 72;
                const __nv_bfloat16* Al = sAlo + rg * 32 * 72;
                const __nv_bfloat16* B0h = sBhi + (nh * 32) * 72;
                const __nv_bfloat16* B1h = sBhi + (nh * 32 + 16) * 72;
                const __nv_bfloat16* B0l = sBlo + (nh * 32) * 72;
                const __nv_bfloat16* B1l = sBlo + (nh * 32 + 16) * 72;
                #pragma unroll
                for (int kt = 0; kt < 4; ++kt) {
                    wm::fragment<wm::matrix_a, 16, 16, 16, __nv_bfloat16, wm::row_major> ah0, ah1, al0, al1;
                    wm::load_matrix_sync(ah0, Ah + kt * 16, 72);
                    wm::load_matrix_sync(ah1, Ah + 16 * 72 + kt * 16, 72);
                    wm::load_matrix_sync(al0, Al + kt * 16, 72);
                    wm::load_matrix_sync(al1, Al + 16 * 72 + kt * 16, 72);
                    wm::fragment<wm::matrix_b, 16, 16, 16, __nv_bfloat16, wm::col_major> b;
                    wm::load_matrix_sync(b, B0h + kt * 16, 72);
                    wm::mma_sync(c00, ah0, b, c00);
                    wm::mma_sync(c10, ah1, b, c10);
                    wm::mma_sync(c00, al0, b, c00);
                    wm::mma_sync(c10, al1, b, c10);
                    wm::load_matrix_sync(b, B1h + kt * 16, 72);
                    wm::mma_sync(c01, ah0, b, c01);
                    wm::mma_sync(c11, ah1, b, c11);
                    wm::mma_sync(c01, al0, b, c01);
                    wm::mma_sync(c11, al1, b, c11);
                    wm::load_matrix_sync(b, B0l + kt * 16, 72);
                    wm::mma_sync(c00, ah0, b, c00);
                    wm::mma_sync(c10, ah1, b, c10);
                    wm::load_matrix_sync(b, B1l + kt * 16, 72);
                    wm::mma_sync(c01, ah0, b, c01);
                    wm::mma_sync(c11, ah1, b, c11);
                }
            }
            __syncthreads();
            wm::store_matrix_sync(sAcc + (rg * 32) * 68 + nh * 32, c00, 68, wm::mem_row_major);
            wm::store_matrix_sync(sAcc + (rg * 32) * 68 + nh * 32 + 16, c01, 68, wm::mem_row_major);
            wm::store_matrix_sync(sAcc + (rg * 32 + 16) * 68 + nh * 32, c10, 68, wm::mem_row_major);
            wm::store_matrix_sync(sAcc + (rg * 32 + 16) * 68 + nh * 32 + 16, c11, 68, wm::mem_row_major);
            __syncthreads();
            if (tid < 128) {
                float s0 = spb2[0], s1 = spb2[1], s2 = spb2[2];
                #pragma unroll
                for (int q = 0; q < 16; ++q) {
                    F4U tt; tt.v = *(const float4*)(sAcc + tid * 68 + q * 4);
                    #pragma unroll
                    for (int c = 0; c < 4; ++c) {
                        int j = q * 4 + c;
                        float v = silu_f(tt.f[c] + sbc[j]);
                        s0 += v * spW2[j * 3 + 0];
                        s1 += v * spW2[j * 3 + 1];
                        s2 += v * spW2[j * 3 + 2];
                    }
                }
                int dn = sdst[tid];
                atomicAdd(&d_aggpm[dn * 3 + 0], sdv[tid * 3 + 0] * s0);
                atomicAdd(&d_aggpm[dn * 3 + 1], sdv[tid * 3 + 1] * s1);
                atomicAdd(&d_aggpm[dn * 3 + 2], sdv[tid * 3 + 2] * s2);
            }
        }
    }
    grid_barrier((3u * l + 2u) * gridDim.x);

    // ================= phase 3: node update (FFMA2) =================
    {
        float* smf = (float*)smem;
        float* sfA  = smf;                   // 64*132
        float* sfB  = sfA + 64 * 132;        // 64*68
        float* sWm  = sfB + 64 * 68;
        float* sW1a = sWm + 64 * 68;
        float* sW2t = sW1a + 64 * 68;
        float* sb1  = sW2t + 64 * 68;
        float* sb2  = sb1 + 64;
        float* sb3  = sb2 + 64;
        float* sAm  = sb3 + 64;
        float* sBm  = sAm + 64;
        float* sb2m = sBm + 64;
        float* sfnz = sb2m + 64;
        for (int idx = tid; idx < 64 * 64; idx += 256) {
            int k = idx >> 6, j = idx & 63;
            sWm[j * 68 + k]  = W2[idx];
            sW1a[j * 68 + k] = uW1[idx];
            sW2t[j * 68 + k] = uW2[idx];
        }
        if (tid < 64) {
            sb1[tid] = ub1[tid]; sb2[tid] = ub2[tid]; sb3[tid] = ub3[tid];
            float mu  = d_bnsum[l * 64 + tid]   * (1.0f / (float)EE);
            float var = d_bnsumsq[l * 64 + tid] * (1.0f / (float)EE) - mu * mu;
            float inv = rsqrtf(var + BN_EPS);
            float A = gamma[tid] * inv;
            sAm[tid] = A;
            sBm[tid] = beta[tid] - mu * A;
            sb2m[tid] = b2[tid];
        }
        for (int t = blockIdx.x; t < ND_TILES; t += gridDim.x) {
            int base = t * 64;
            __syncthreads();
            for (int idx = tid; idx < 64 * 16; idx += 256) {
                int e = idx >> 4, q = idx & 15;
                int n = base + e;
                float4 hv = make_float4(0.f, 0.f, 0.f, 0.f);
                F4U tt; tt.v = make_float4(0.f, 0.f, 0.f, 0.f);
                if (n < NN) {
                    hv = *(const float4*)(d_h + n * 64 + q * 4);
                    tt.v = *(const float4*)(d_summ1 + n * 64 + q * 4);
                    *(float4*)(d_summ1 + n * 64 + q * 4) = make_float4(0.f, 0.f, 0.f, 0.f);
                    float inv = d_invc[n];
                    float f = (d_counts[n] > 0) ? 1.0f : 0.0f;
                    #pragma unroll
                    for (int c = 0; c < 4; ++c)
                        tt.f[c] = sAm[q * 4 + c] * (tt.f[c] * inv) + f * sBm[q * 4 + c];
                }
                *(float4*)(sfA + e * 132 + q * 4) = hv;
                *(float4*)(sfB + e * 68 + q * 4) = tt.v;
            }
            if (tid < 64) {
                int n = base + tid;
                float f = 0.0f;
                if (n < NN) {
                    f = (d_counts[n] > 0) ? 1.0f : 0.0f;
                    float inv = d_invc[n];
                    #pragma unroll
                    for (int c = 0; c < 3; ++c) {
                        d_pos[n * 3 + c] += d_aggpm[n * 3 + c] * inv;
                        d_aggpm[n * 3 + c] = 0.0f;
                    }
                }
                sfnz[tid] = f;
            }
            __syncthreads();
            {   // agg = mnorm @ mW2 + f*mb2 -> sfA[:,64:128]
                ull a0[4][4] = {};
                gemm_acc4<68, 68>(sfB, sWm, 64, et, jt, a0);
                #pragma unroll
                for (int e = 0; e < 4; ++e) {
                    int er = et + 16 * e;
                    float f = sfnz[er];
                    F4U o;
                    #pragma unroll
                    for (int j = 0; j < 4; ++j)
                        o.f[j] = lane_sum(a0[e][j]) + f * sb2m[jt * 4 + j];
                    *(float4*)(sfA + er * 132 + 64 + jt * 4) = o.v;
                }
            }
            __syncthreads();
            ull a1[4][4] = {};
            gemm_acc4<132, 68>(sfA, sW1a, 64, et, jt, a1);
            {   // uW1 rows 64..127 from gmem (L2-hot broadcast)
                const float* fb = sfA + et * 132 + 64;
                #pragma unroll 2
                for (int k0 = 0; k0 < 64; k0 += 4) {
                    ull ww[4][2];
                    #pragma unroll
                    for (int j = 0; j < 4; ++j) {
                        F4U tw;
                        tw.f[0] = uW1[(64 + k0 + 0) * 64 + jt * 4 + j];
                        tw.f[1] = uW1[(64 + k0 + 1) * 64 + jt * 4 + j];
                        tw.f[2] = uW1[(64 + k0 + 2) * 64 + jt * 4 + j];
                        tw.f[3] = uW1[(64 + k0 + 3) * 64 + jt * 4 + j];
                        ww[j][0] = tw.u[0]; ww[j][1] = tw.u[1];
                    }
                    #pragma unroll
                    for (int e = 0; e < 4; ++e) {
                        F4U tf; tf.v = *(const float4*)(fb + e * 16 * 132 + k0);
                        #pragma unroll
                        for (int j = 0; j < 4; ++j) {
                            a1[e][j] = ffma2(tf.u[0], ww[j][0], a1[e][j]);
                            a1[e][j] = ffma2(tf.u[1], ww[j][1], a1[e][j]);
                        }
                    }
                }
            }
            __syncthreads();
            #pragma unroll
            for (int e = 0; e < 4; ++e) {
                F4U o;
                #pragma unroll
                for (int j = 0; j < 4; ++j)
                    o.f[j] = silu_f(lane_sum(a1[e][j]) + sb1[jt * 4 + j]);
                *(float4*)(sfB + (et + 16 * e) * 68 + jt * 4) = o.v;
            }
            __syncthreads();
            {
                ull a2[4][4] = {};
                gemm_acc4<68, 68>(sfB, sW2t, 64, et, jt, a2);
                #pragma unroll
                for (int e = 0; e < 4; ++e) {
                    F4U o;
                    #pragma unroll
                    for (int j = 0; j < 4; ++j)
                        o.f[j] = silu_f(lane_sum(a2[e][j]) + sb2[jt * 4 + j]);
                    *(float4*)(sfA + (et + 16 * e) * 132 + jt * 4) = o.v;
                }
            }
            __syncthreads();
            {   // h += v @ uW3 + b3  (uW3 from gmem)
                ull a3[4][4] = {};
                const float* fb = sfA + et * 132;
                #pragma unroll 2
                for (int k0 = 0; k0 < 64; k0 += 4) {
                    ull ww[4][2];
                    #pragma unroll
                    for (int j = 0; j < 4; ++j) {
                        F4U tw;
                        tw.f[0] = uW3[(k0 + 0) * 64 + jt * 4 + j];
                        tw.f[1] = uW3[(k0 + 1) * 64 + jt * 4 + j];
                        tw.f[2] = uW3[(k0 + 2) * 64 + jt * 4 + j];
                        tw.f[3] = uW3[(k0 + 3) * 64 + jt * 4 + j];
                        ww[j][0] = tw.u[0]; ww[j][1] = tw.u[1];
                    }
                    #pragma unroll
                    for (int e = 0; e < 4; ++e) {
                        F4U tf; tf.v = *(const float4*)(fb + e * 16 * 132 + k0);
                        #pragma unroll
                        for (int j = 0; j < 4; ++j) {
                            a3[e][j] = ffma2(tf.u[0], ww[j][0], a3[e][j]);
                            a3[e][j] = ffma2(tf.u[1], ww[j][1], a3[e][j]);
                        }
                    }
                }
                #pragma unroll
                for (int e = 0; e < 4; ++e) {
                    int n = base + et + 16 * e;
                    if (n < NN) {
                        F4U h; h.v = *(const float4*)(d_h + n * 64 + jt * 4);
                        F4U o;
                        #pragma unroll
                        for (int j = 0; j < 4; ++j)
                            o.f[j] = h.f[j] + lane_sum(a3[e][j]) + sb3[jt * 4 + j];
                        *(float4*)(d_h + n * 64 + jt * 4) = o.v;
                        __nv_bfloat16 hb[4]; float lo[4];
                        #pragma unroll
                        for (int j = 0; j < 4; ++j) {
                            hb[j] = __float2bfloat16(o.f[j]);
                            lo[j] = o.f[j] - __bfloat162float(hb[j]);
                        }
                        uint2 H, L;
                        H.x = pack_bf(hb[0], hb[1]); H.y = pack_bf(hb[2], hb[3]);
                        L.x = pack_bf(__float2bfloat16(lo[0]), __float2bfloat16(lo[1]));
                        L.y = pack_bf(__float2bfloat16(lo[2]), __float2bfloat16(lo[3]));
                        *(uint2*)(d_hhi + n * 64 + jt * 4) = H;
                        *(uint2*)(d_hlo + n * 64 + jt * 4) = L;
                    }
                }
            }
        }
    }
    grid_barrier((3u * l + 3u) * gridDim.x);
}

// ---------------- energy MLP ----------------
#define EN_SMEM ((64*68*2 + 64*68*2 + 64 + 64 + 64 + 4) * (int)sizeof(float))
__global__ void energy_kernel(const float* __restrict__ W1, const float* __restrict__ b1,
                              const float* __restrict__ W2, const float* __restrict__ b2,
                              const float* __restrict__ W3, const float* __restrict__ b3,
                              float* __restrict__ out) {
    extern __shared__ float sm[];
    float* sfA  = sm;
    float* sfB  = sfA + 64 * 68;
    float* sW1t = sfB + 64 * 68;
    float* sW2t = sW1t + 64 * 68;
    float* sW3  = sW2t + 64 * 68;
    float* sb1  = sW3 + 64;
    float* sb2  = sb1 + 64;
    float* sb3  = sb2 + 64;
    int tid = threadIdx.x;
    int base = blockIdx.x * 64;
    for (int idx = tid; idx < 64 * 64; idx += 256) {
        int k = idx >> 6, j = idx & 63;
        sW1t[j * 68 + k] = W1[idx];
        sW2t[j * 68 + k] = W2[idx];
    }
    if (tid < 64) { sW3[tid] = W3[tid]; sb1[tid] = b1[tid]; sb2[tid] = b2[tid]; }
    if (tid == 0) sb3[0] = b3[0];
    for (int idx = tid; idx < 64 * 16; idx += 256) {
        int e = idx >> 4, q = idx & 15;
        int n = base + e;
        float4 v = (n < NN) ? *(const float4*)(d_h + n * 64 + q * 4)
                            : make_float4(0.f, 0.f, 0.f, 0.f);
        *(float4*)(sfA + e * 68 + q * 4) = v;
    }
    __syncthreads();
    int et = tid & 15, jt = tid >> 4;
    {
        ull acc[4][4] = {};
        gemm_acc4<68, 68>(sfA, sW1t, 64, et, jt, acc);
        #pragma unroll
        for (int e = 0; e < 4; ++e) {
            F4U o;
            #pragma unroll
            for (int j = 0; j < 4; ++j)
                o.f[j] = silu_f(lane_sum(acc[e][j]) + sb1[jt * 4 + j]);
            *(float4*)(sfB + (et + 16 * e) * 68 + jt * 4) = o.v;
        }
    }
    __syncthreads();
    {
        ull acc[4][4] = {};
        gemm_acc4<68, 68>(sfB, sW2t, 64, et, jt, acc);
        #pragma unroll
        for (int e = 0; e < 4; ++e) {
            F4U o;
            #pragma unroll
            for (int j = 0; j < 4; ++j)
                o.f[j] = silu_f(lane_sum(acc[e][j]) + sb2[jt * 4 + j]);
            *(float4*)(sfA + (et + 16 * e) * 68 + jt * 4) = o.v;
        }
    }
    __syncthreads();
    if (tid < 64) {
        int n = base + tid;
        if (n < NN) {
            float s = sb3[0];
            #pragma unroll
            for (int q = 0; q < 16; ++q) {
                F4U t; t.v = *(const float4*)(sfA + tid * 68 + q * 4);
                #pragma unroll
                for (int c = 0; c < 4; ++c) s += t.f[c] * sW3[q * 4 + c];
            }
            out[n] = s;
        }
    }
}

// ---------------- launch ----------------
extern "C" void kernel_launch(void* const* d_in, const int* in_sizes, int n_in,
                              void* d_out, int out_size) {
    const float* h_in   = (const float*)d_in[0];
    const float* pos    = (const float*)d_in[1];
    const float* cell   = (const float*)d_in[2];
    const int*   esrc   = (const int*)d_in[3];
    const int*   edst   = (const int*)d_in[4];
    const float* emb_W1 = (const float*)d_in[5];
    const float* emb_b1 = (const float*)d_in[6];
    const float* emb_W2 = (const float*)d_in[7];
    const float* emb_b2 = (const float*)d_in[8];
    const float* msg_W1 = (const float*)d_in[9];
    const float* msg_b1 = (const float*)d_in[10];
    const float* bn_g   = (const float*)d_in[11];
    const float* bn_b   = (const float*)d_in[12];
    const float* msg_W2 = (const float*)d_in[13];
    const float* msg_b2 = (const float*)d_in[14];
    const float* upd_W1 = (const float*)d_in[15];
    const float* upd_b1 = (const float*)d_in[16];
    const float* upd_W2 = (const float*)d_in[17];
    const float* upd_b2 = (const float*)d_in[18];
    const float* upd_W3 = (const float*)d_in[19];
    const float* upd_b3 = (const float*)d_in[20];
    const float* pos_W1 = (const float*)d_in[21];
    const float* pos_b1 = (const float*)d_in[22];
    const float* pos_W2 = (const float*)d_in[23];
    const float* pos_b2 = (const float*)d_in[24];
    const float* en_W1  = (const float*)d_in[25];
    const float* en_b1  = (const float*)d_in[26];
    const float* en_W2  = (const float*)d_in[27];
    const float* en_b2  = (const float*)d_in[28];
    const float* en_W3  = (const float*)d_in[29];
    const float* en_b3  = (const float*)d_in[30];
    float* out = (float*)d_out;

    static int n_sms = 0;
    if (!n_sms) {
        if (cudaDeviceGetAttribute(&n_sms, cudaDevAttrMultiProcessorCount, 0) != cudaSuccess || n_sms <= 0)
            n_sms = 148;
        cudaFuncSetAttribute(embed_kernel,  cudaFuncAttributeMaxDynamicSharedMemorySize, EM_SMEM);
        cudaFuncSetAttribute(layer_kernel,  cudaFuncAttributeMaxDynamicSharedMemorySize, LY_SMEM);
        cudaFuncSetAttribute(energy_kernel, cudaFuncAttributeMaxDynamicSharedMemorySize, EN_SMEM);
    }
    const int LY_GRID = 2 * n_sms;   // co-resident (2 CTAs/SM) -> barrier-safe

    init_kernel<<<(NN * F + 255) / 256, 256>>>(pos);
    count_kernel<<<(EE + 255) / 256, 256>>>(edst);
    inv_kernel<<<(NN + 255) / 256, 256>>>();
    wconv_kernel<<<(NL * F * 128 + 255) / 256, 256>>>(msg_W1);
    embed_kernel<<<313, 256, EM_SMEM>>>(h_in, emb_W1, emb_b1, emb_W2, emb_b2);

    for (int l = 0; l < NL; ++l) {
        layer_kernel<<<LY_GRID, 256, LY_SMEM>>>(
            esrc, edst, cell,
            msg_W1 + l * (2 * F + 1) * F, msg_b1 + l * F,
            bn_g + l * F, bn_b + l * F,
            msg_W2 + l * F * F, msg_b2 + l * F,
            pos_W1 + l * F * F, pos_b1 + l * F,
            pos_W2 + l * F * DIM, pos_b2 + l * DIM,
            upd_W1 + l * 2 * F * F, upd_b1 + l * F,
            upd_W2 + l * F * F, upd_b2 + l * F,
            upd_W3 + l * F * F, upd_b3 + l * F, l);
    }
    energy_kernel<<<313, 256, EN_SMEM>>>(en_W1, en_b1, en_W2, en_b2, en_W3, en_b3, out);
}

// round 17
// speedup vs baseline: 1.1519x; 1.1519x over previous
#include <cuda_runtime.h>
#include <cuda_bf16.h>
#include <mma.h>
#include <cstdint>

namespace wm = nvcuda::wmma;

#define NN 20000
#define EE 160000
#define FIN 9
#define F 64
#define NL 7
#define DIM 3
#define BN_EPS 1e-5f
#define NT_T128 1250

typedef unsigned long long ull;
union F4U { float4 v; ull u[2]; float f[4]; };

// ---------------- device scratch ----------------
__device__ float d_h[NN * F];
__device__ __nv_bfloat16 d_hhi[NN * F];
__device__ __nv_bfloat16 d_hlo[NN * F];
__device__ float d_pos[NN * DIM];
__device__ __nv_bfloat16 d_m1hi[EE * F];
__device__ __nv_bfloat16 d_m1lo[EE * F];
__device__ float d_dvec[EE * DIM];
__device__ float d_summ1[NN * F];
__device__ float d_aggpm[NN * DIM];
__device__ int   d_counts[NN];
__device__ float d_invc[NN];
__device__ float d_bnsum[NL * F];
__device__ float d_bnsumsq[NL * F];
__device__ __nv_bfloat16 d_w1hi[NL * F * 128];   // [l][j][k] (col-major KxN for wmma B)
__device__ __nv_bfloat16 d_w1lo[NL * F * 128];

// silu via single-MUFU tanh.approx: silu(x) = 0.5x * (1 + tanh(x/2))
__device__ __forceinline__ float silu_f(float x) {
    float t;
    asm("tanh.approx.f32 %0, %1;" : "=f"(t) : "f"(x * 0.5f));
    float hx = 0.5f * x;
    return fmaf(hx, t, hx);
}

__device__ __forceinline__ ull ffma2(ull a, ull b, ull c) {
    ull d;
    asm("fma.rn.f32x2 %0, %1, %2, %3;" : "=l"(d) : "l"(a), "l"(b), "l"(c));
    return d;
}
__device__ __forceinline__ float lane_sum(ull a) {
    float lo = __uint_as_float((unsigned)(a & 0xffffffffull));
    float hi = __uint_as_float((unsigned)(a >> 32));
    return lo + hi;
}
__device__ __forceinline__ void red_add_v4(float* p, float a, float b, float c, float d) {
    asm volatile("red.global.add.v4.f32 [%0], {%1,%2,%3,%4};"
                 :: "l"(p), "f"(a), "f"(b), "f"(c), "f"(d) : "memory");
}
__device__ __forceinline__ unsigned pack_bf(__nv_bfloat16 a, __nv_bfloat16 b) {
    __nv_bfloat162 t(a, b); return *(unsigned*)&t;
}

// ---------------- FFMA2 GEMM core ----------------
template<int PF, int PW>
__device__ __forceinline__ void gemm_acc4(const float* __restrict__ sf,
                                          const float* __restrict__ sWt,
                                          int kmax, int et, int jt, ull acc[4][4]) {
    const float* fb = sf + et * PF;
    const float* wb = sWt + (jt * 4) * PW;
    #pragma unroll 2
    for (int k0 = 0; k0 < kmax; k0 += 4) {
        ull w[4][2];
        #pragma unroll
        for (int j = 0; j < 4; ++j) {
            F4U t; t.v = *(const float4*)(wb + j * PW + k0);
            w[j][0] = t.u[0]; w[j][1] = t.u[1];
        }
        #pragma unroll
        for (int e = 0; e < 4; ++e) {
            F4U t; t.v = *(const float4*)(fb + e * 16 * PF + k0);
            #pragma unroll
            for (int j = 0; j < 4; ++j) {
                acc[e][j] = ffma2(t.u[0], w[j][0], acc[e][j]);
                acc[e][j] = ffma2(t.u[1], w[j][1], acc[e][j]);
            }
        }
    }
}

// ---------------- init ----------------
__global__ void init_kernel(const float* __restrict__ pos_in) {
    int i = blockIdx.x * blockDim.x + threadIdx.x;
    if (i < NN * F) d_summ1[i] = 0.0f;
    if (i < NN * DIM) { d_aggpm[i] = 0.0f; d_pos[i] = pos_in[i]; }
    if (i < NN) d_counts[i] = 0;
    if (i < NL * F) { d_bnsum[i] = 0.0f; d_bnsumsq[i] = 0.0f; }
}
__global__ void count_kernel(const int* __restrict__ edge_dst) {
    int i = blockIdx.x * blockDim.x + threadIdx.x;
    if (i < EE) atomicAdd(&d_counts[edge_dst[i]], 1);
}
__global__ void inv_kernel() {
    int i = blockIdx.x * blockDim.x + threadIdx.x;
    if (i < NN) d_invc[i] = 1.0f / fmaxf((float)d_counts[i], 1.0f);
}
__global__ void wconv_kernel(const float* __restrict__ msg_W1) {
    int idx = blockIdx.x * blockDim.x + threadIdx.x;
    if (idx >= NL * F * 128) return;
    int l = idx >> 13, r = idx & 8191;
    int j = r >> 7, k = r & 127;
    float v = msg_W1[l * 8256 + k * 64 + j];
    __nv_bfloat16 h = __float2bfloat16(v);
    d_w1hi[idx] = h;
    d_w1lo[idx] = __float2bfloat16(v - __bfloat162float(h));
}

// ---------------- embedding (FFMA2) + h hi/lo emission ----------------
#define EM_SMEM ((64*12 + 64*12 + 64*68 + 64*68 + 128) * (int)sizeof(float))
__global__ void embed_kernel(const float* __restrict__ h_in,
                             const float* __restrict__ W1, const float* __restrict__ b1,
                             const float* __restrict__ W2, const float* __restrict__ b2) {
    extern __shared__ float sm[];
    float* sf   = sm;
    float* sW1t = sf + 64 * 12;
    float* sfB  = sW1t + 64 * 12;
    float* sW2t = sfB + 64 * 68;
    float* sb1  = sW2t + 64 * 68;
    float* sb2  = sb1 + 64;
    int tid = threadIdx.x;
    int base = blockIdx.x * 64;
    for (int idx = tid; idx < 64 * 12; idx += 256) {
        int j = idx / 12, k = idx - j * 12;
        sW1t[idx] = (k < FIN) ? W1[k * 64 + j] : 0.0f;
    }
    for (int idx = tid; idx < 64 * 64; idx += 256) {
        int k = idx >> 6, j = idx & 63;
        sW2t[j * 68 + k] = W2[idx];
    }
    if (tid < 64) { sb1[tid] = b1[tid]; sb2[tid] = b2[tid]; }
    for (int idx = tid; idx < 64 * 12; idx += 256) {
        int e = idx / 12, k = idx - e * 12;
        int n = base + e;
        sf[idx] = (k < FIN && n < NN) ? h_in[n * FIN + k] : 0.0f;
    }
    __syncthreads();
    int et = tid & 15, jt = tid >> 4;
    {
        ull acc[4][4] = {};
        gemm_acc4<12, 12>(sf, sW1t, 12, et, jt, acc);
        #pragma unroll
        for (int e = 0; e < 4; ++e) {
            F4U o;
            #pragma unroll
            for (int j = 0; j < 4; ++j)
                o.f[j] = silu_f(lane_sum(acc[e][j]) + sb1[jt * 4 + j]);
            *(float4*)(sfB + (et + 16 * e) * 68 + jt * 4) = o.v;
        }
    }
    __syncthreads();
    {
        ull acc[4][4] = {};
        gemm_acc4<68, 68>(sfB, sW2t, 64, et, jt, acc);
        #pragma unroll
        for (int e = 0; e < 4; ++e) {
            int n = base + et + 16 * e;
            if (n < NN) {
                F4U o;
                #pragma unroll
                for (int j = 0; j < 4; ++j)
                    o.f[j] = lane_sum(acc[e][j]) + sb2[jt * 4 + j];
                *(float4*)(d_h + n * 64 + jt * 4) = o.v;
                __nv_bfloat16 hb[4]; float lo[4];
                #pragma unroll
                for (int j = 0; j < 4; ++j) {
                    hb[j] = __float2bfloat16(o.f[j]);
                    lo[j] = o.f[j] - __bfloat162float(hb[j]);
                }
                uint2 H, L;
                H.x = pack_bf(hb[0], hb[1]); H.y = pack_bf(hb[2], hb[3]);
                L.x = pack_bf(__float2bfloat16(lo[0]), __float2bfloat16(lo[1]));
                L.y = pack_bf(__float2bfloat16(lo[2]), __float2bfloat16(lo[3]));
                *(uint2*)(d_hhi + n * 64 + jt * 4) = H;
                *(uint2*)(d_hlo + n * 64 + jt * 4) = L;
            }
        }
    }
}

// ---------------- pass1: wmma + fused BN stats ----------------
#define P1_SMEM 106496
__global__ void __launch_bounds__(256, 2)
pass1_wmma(const int* __restrict__ esrc, const int* __restrict__ edst,
           const float* __restrict__ cell,
           const float* __restrict__ W1, const float* __restrict__ b1, int l) {
    extern __shared__ char smem[];
    __nv_bfloat16* sAhi = (__nv_bfloat16*)(smem);
    __nv_bfloat16* sAlo = (__nv_bfloat16*)(smem + 34816);
    __nv_bfloat16* sBhi = (__nv_bfloat16*)(smem + 69632);
    __nv_bfloat16* sBlo = (__nv_bfloat16*)(smem + 87040);
    float* sAcc  = (float*)(smem);
    float* w129  = (float*)(smem + 104448);
    float* sb1   = (float*)(smem + 104704);
    float* sdist = (float*)(smem + 104960);
    int*   sdst  = (int*)(smem + 105472);
    int*   ssrc  = (int*)(smem + 105984);
    int tid = threadIdx.x;
    for (int i = tid; i < 64 * 16; i += 256) {
        int j = i >> 4, c = i & 15;
        *(uint4*)(sBhi + j * 136 + c * 8) = ((const uint4*)(d_w1hi + l * 8192 + j * 128))[c];
        *(uint4*)(sBlo + j * 136 + c * 8) = ((const uint4*)(d_w1lo + l * 8192 + j * 128))[c];
    }
    if (tid < 64) { w129[tid] = W1[128 * 64 + tid]; sb1[tid] = b1[tid]; }
    int w = tid >> 5, rg = w >> 1, nh = w & 1;
    int cb = tid >> 5, el = tid & 31, j0 = cb * 8;
    float lsum[8] = {0,0,0,0,0,0,0,0}, lsq[8] = {0,0,0,0,0,0,0,0};

    for (int t = blockIdx.x; t < NT_T128; t += gridDim.x) {
        int base = t * 128;
        __syncthreads();
        if (tid < 128) {
            int ge = base + tid;
            int dn = edst[ge], sn = esrc[ge];
            sdst[tid] = dn; ssrc[tid] = sn;
            float dv0 = d_pos[dn * 3 + 0] - d_pos[sn * 3 + 0] + cell[ge * 3 + 0];
            float dv1 = d_pos[dn * 3 + 1] - d_pos[sn * 3 + 1] + cell[ge * 3 + 1];
            float dv2 = d_pos[dn * 3 + 2] - d_pos[sn * 3 + 2] + cell[ge * 3 + 2];
            d_dvec[ge * 3 + 0] = dv0; d_dvec[ge * 3 + 1] = dv1; d_dvec[ge * 3 + 2] = dv2;
            sdist[tid] = dv0 + dv1 + dv2;
        }
        __syncthreads();
        for (int idx = tid; idx < 128 * 32; idx += 256) {
            int e = idx >> 5, q = idx & 31, c = q & 7;
            int n = (q & 8) ? ssrc[e] : sdst[e];
            const uint4* src = (q & 16) ? (const uint4*)(d_hlo + n * 64)
                                        : (const uint4*)(d_hhi + n * 64);
            __nv_bfloat16* dp = ((q & 16) ? sAlo : sAhi) + e * 136 + ((q & 8) ? 64 : 0) + c * 8;
            *(uint4*)dp = src[c];
        }
        __syncthreads();
        wm::fragment<wm::accumulator, 16, 16, 16, float> c00, c01, c10, c11;
        wm::fill_fragment(c00, 0.0f); wm::fill_fragment(c01, 0.0f);
        wm::fill_fragment(c10, 0.0f); wm::fill_fragment(c11, 0.0f);
        {
            const __nv_bfloat16* Ah = sAhi + rg * 32 * 136;
            const __nv_bfloat16* Al = sAlo + rg * 32 * 136;
            const __nv_bfloat16* B0h = sBhi + (nh * 32) * 136;
            const __nv_bfloat16* B1h = sBhi + (nh * 32 + 16) * 136;
            const __nv_bfloat16* B0l = sBlo + (nh * 32) * 136;
            const __nv_bfloat16* B1l = sBlo + (nh * 32 + 16) * 136;
            #pragma unroll
            for (int kt = 0; kt < 8; ++kt) {
                wm::fragment<wm::matrix_a, 16, 16, 16, __nv_bfloat16, wm::row_major> ah0, ah1, al0, al1;
                wm::load_matrix_sync(ah0, Ah + kt * 16, 136);
                wm::load_matrix_sync(ah1, Ah + 16 * 136 + kt * 16, 136);
                wm::load_matrix_sync(al0, Al + kt * 16, 136);
                wm::load_matrix_sync(al1, Al + 16 * 136 + kt * 16, 136);
                wm::fragment<wm::matrix_b, 16, 16, 16, __nv_bfloat16, wm::col_major> b;
                wm::load_matrix_sync(b, B0h + kt * 16, 136);
                wm::mma_sync(c00, ah0, b, c00);
                wm::mma_sync(c10, ah1, b, c10);
                wm::mma_sync(c00, al0, b, c00);
                wm::mma_sync(c10, al1, b, c10);
                wm::load_matrix_sync(b, B1h + kt * 16, 136);
                wm::mma_sync(c01, ah0, b, c01);
                wm::mma_sync(c11, ah1, b, c11);
                wm::mma_sync(c01, al0, b, c01);
                wm::mma_sync(c11, al1, b, c11);
                wm::load_matrix_sync(b, B0l + kt * 16, 136);
                wm::mma_sync(c00, ah0, b, c00);
                wm::mma_sync(c10, ah1, b, c10);
                wm::load_matrix_sync(b, B1l + kt * 16, 136);
                wm::mma_sync(c01, ah0, b, c01);
                wm::mma_sync(c11, ah1, b, c11);
            }
        }
        __syncthreads();
        wm::store_matrix_sync(sAcc + (rg * 32) * 68 + nh * 32, c00, 68, wm::mem_row_major);
        wm::store_matrix_sync(sAcc + (rg * 32) * 68 + nh * 32 + 16, c01, 68, wm::mem_row_major);
        wm::store_matrix_sync(sAcc + (rg * 32 + 16) * 68 + nh * 32, c10, 68, wm::mem_row_major);
        wm::store_matrix_sync(sAcc + (rg * 32 + 16) * 68 + nh * 32 + 16, c11, 68, wm::mem_row_major);
        __syncthreads();
        #pragma unroll
        for (int i = 0; i < 4; ++i) {
            int e = el + 32 * i;
            int ge = base + e;
            int dn = sdst[e];
            float dist = sdist[e];
            float mv[8];
            __nv_bfloat16 hb[8], lb[8];
            #pragma unroll
            for (int jj = 0; jj < 8; ++jj) {
                int j = j0 + jj;
                float v = sAcc[e * 68 + j] + dist * w129[j] + sb1[j];
                v = silu_f(v);
                mv[jj] = v;
                lsum[jj] += v; lsq[jj] += v * v;
                hb[jj] = __float2bfloat16(v);
                lb[jj] = __float2bfloat16(v - __bfloat162float(hb[jj]));
            }
            uint4 H, L;
            H.x = pack_bf(hb[0], hb[1]); H.y = pack_bf(hb[2], hb[3]);
            H.z = pack_bf(hb[4], hb[5]); H.w = pack_bf(hb[6], hb[7]);
            L.x = pack_bf(lb[0], lb[1]); L.y = pack_bf(lb[2], lb[3]);
            L.z = pack_bf(lb[4], lb[5]); L.w = pack_bf(lb[6], lb[7]);
            ((uint4*)(d_m1hi + (size_t)ge * 64))[cb] = H;
            ((uint4*)(d_m1lo + (size_t)ge * 64))[cb] = L;
            red_add_v4(d_summ1 + dn * 64 + j0,     mv[0], mv[1], mv[2], mv[3]);
            red_add_v4(d_summ1 + dn * 64 + j0 + 4, mv[4], mv[5], mv[6], mv[7]);
        }
    }
    #pragma unroll
    for (int jj = 0; jj < 8; ++jj) {
        #pragma unroll
        for (int o = 1; o < 32; o <<= 1) {
            lsum[jj] += __shfl_xor_sync(0xffffffffu, lsum[jj], o);
            lsq[jj]  += __shfl_xor_sync(0xffffffffu, lsq[jj], o);
        }
    }
    if (el == 0) {
        #pragma unroll
        for (int jj = 0; jj < 8; ++jj) {
            atomicAdd(&d_bnsum[l * 64 + j0 + jj], lsum[jj]);
            atomicAdd(&d_bnsumsq[l * 64 + j0 + jj], lsq[jj]);
        }
    }
}

// ---------------- pass2: wmma, BN prep fused in prologue ----------------
#define P2_SMEM 59152
__global__ void __launch_bounds__(256, 2)
pass2_wmma(const int* __restrict__ edst,
           const float* __restrict__ gamma, const float* __restrict__ beta,
           const float* __restrict__ W2, const float* __restrict__ b2,
           const float* __restrict__ pW1, const float* __restrict__ pb1,
           const float* __restrict__ pW2, const float* __restrict__ pb2, int l) {
    extern __shared__ char smem[];
    __nv_bfloat16* sAhi = (__nv_bfloat16*)(smem);
    __nv_bfloat16* sAlo = (__nv_bfloat16*)(smem + 18432);
    __nv_bfloat16* sBhi = (__nv_bfloat16*)(smem + 36864);
    __nv_bfloat16* sBlo = (__nv_bfloat16*)(smem + 46080);
    float* sAcc = (float*)(smem);
    float* sW2f = (float*)(smem);            // prologue scratch
    float* spW1f = (float*)(smem + 18432);   // prologue scratch
    float* sbc  = (float*)(smem + 55296);
    float* spW2 = (float*)(smem + 55552);
    float* spb2 = (float*)(smem + 56320);
    float* sdv  = (float*)(smem + 56336);
    int*   sdst = (int*)(smem + 57872);
    float* sA   = (float*)(smem + 58384);
    float* sB   = (float*)(smem + 58640);
    float* sv   = (float*)(smem + 58896);
    int tid = threadIdx.x;
    for (int idx = tid; idx < 4096; idx += 256) {
        sW2f[idx] = W2[idx];
        spW1f[idx] = pW1[idx];
    }
    for (int i = tid; i < 192; i += 256) spW2[i] = pW2[i];
    if (tid < 3) spb2[tid] = pb2[tid];
    if (tid < 64) {
        float mu  = d_bnsum[l * 64 + tid]   * (1.0f / (float)EE);
        float var = d_bnsumsq[l * 64 + tid] * (1.0f / (float)EE) - mu * mu;
        float inv = rsqrtf(var + BN_EPS);
        float A = gamma[tid] * inv;
        sA[tid] = A;
        sB[tid] = beta[tid] - mu * A;
    }
    __syncthreads();
    if (tid < 64) {
        float acc = b2[tid];
        #pragma unroll 8
        for (int k = 0; k < 64; ++k) acc += sB[k] * sW2f[k * 64 + tid];
        sv[tid] = acc;
    }
    __syncthreads();
    if (tid < 64) {
        float acc = pb1[tid];
        #pragma unroll 8
        for (int q = 0; q < 64; ++q) acc += sv[q] * spW1f[q * 64 + tid];
        sbc[tid] = acc;
    }
    for (int idx = tid; idx < 4096; idx += 256) {
        int k = idx >> 6, j = idx & 63;
        float acc = 0.0f;
        #pragma unroll 8
        for (int q = 0; q < 64; ++q) acc += sW2f[k * 64 + q] * spW1f[q * 64 + j];
        float v = sA[k] * acc;
        __nv_bfloat16 h = __float2bfloat16(v);
        sBhi[j * 72 + k] = h;
        sBlo[j * 72 + k] = __float2bfloat16(v - __bfloat162float(h));
    }
    int w = tid >> 5, rg = w >> 1, nh = w & 1;

    for (int t = blockIdx.x; t < NT_T128; t += gridDim.x) {
        int base = t * 128;
        __syncthreads();
        if (tid < 128) sdst[tid] = edst[base + tid];
        for (int i = tid; i < 384; i += 256) sdv[i] = d_dvec[base * 3 + i];
        for (int idx = tid; idx < 128 * 16; idx += 256) {
            int e = idx >> 4, q = idx & 15, c = q & 7;
            const uint4* src = (q & 8) ? (const uint4*)(d_m1lo + (size_t)(base + e) * 64)
                                       : (const uint4*)(d_m1hi + (size_t)(base + e) * 64);
            __nv_bfloat16* dp = ((q & 8) ? sAlo : sAhi) + e * 72 + c * 8;
            *(uint4*)dp = src[c];
        }
        __syncthreads();
        wm::fragment<wm::accumulator, 16, 16, 16, float> c00, c01, c10, c11;
        wm::fill_fragment(c00, 0.0f); wm::fill_fragment(c01, 0.0f);
        wm::fill_fragment(c10, 0.0f); wm::fill_fragment(c11, 0.0f);
        {
            const __nv_bfloat16* Ah = sAhi + rg * 32 * 72;
            const __nv_bfloat16* Al = sAlo + rg * 32 * 72;
            const __nv_bfloat16* B0h = sBhi + (nh * 32) * 72;
            const __nv_bfloat16* B1h = sBhi + (nh * 32 + 16) * 72;
            const __nv_bfloat16* B0l = sBlo + (nh * 32) * 72;
            const __nv_bfloat16* B1l = sBlo + (nh * 32 + 16) * 72;
            #pragma unroll
            for (int kt = 0; kt < 4; ++kt) {
                wm::fragment<wm::matrix_a, 16, 16, 16, __nv_bfloat16, wm::row_major> ah0, ah1, al0, al1;
                wm::load_matrix_sync(ah0, Ah + kt * 16, 72);
                wm::load_matrix_sync(ah1, Ah + 16 * 72 + kt * 16, 72);
                wm::load_matrix_sync(al0, Al + kt * 16, 72);
                wm::load_matrix_sync(al1, Al + 16 * 72 + kt * 16, 72);
                wm::fragment<wm::matrix_b, 16, 16, 16, __nv_bfloat16, wm::col_major> b;
                wm::load_matrix_sync(b, B0h + kt * 16, 72);
                wm::mma_sync(c00, ah0, b, c00);
                wm::mma_sync(c10, ah1, b, c10);
                wm::mma_sync(c00, al0, b, c00);
                wm::mma_sync(c10, al1, b, c10);
                wm::load_matrix_sync(b, B1h + kt * 16, 72);
                wm::mma_sync(c01, ah0, b, c01);
                wm::mma_sync(c11, ah1, b, c11);
                wm::mma_sync(c01, al0, b, c01);
                wm::mma_sync(c11, al1, b, c11);
                wm::load_matrix_sync(b, B0l + kt * 16, 72);
                wm::mma_sync(c00, ah0, b, c00);
                wm::mma_sync(c10, ah1, b, c10);
                wm::load_matrix_sync(b, B1l + kt * 16, 72);
                wm::mma_sync(c01, ah0, b, c01);
                wm::mma_sync(c11, ah1, b, c11);
            }
        }
        __syncthreads();
        wm::store_matrix_sync(sAcc + (rg * 32) * 68 + nh * 32, c00, 68, wm::mem_row_major);
        wm::store_matrix_sync(sAcc + (rg * 32) * 68 + nh * 32 + 16, c01, 68, wm::mem_row_major);
        wm::store_matrix_sync(sAcc + (rg * 32 + 16) * 68 + nh * 32, c10, 68, wm::mem_row_major);
        wm::store_matrix_sync(sAcc + (rg * 32 + 16) * 68 + nh * 32 + 16, c11, 68, wm::mem_row_major);
        __syncthreads();
        if (tid < 128) {
            float s0 = spb2[0], s1 = spb2[1], s2 = spb2[2];
            #pragma unroll
            for (int q = 0; q < 16; ++q) {
                F4U tt; tt.v = *(const float4*)(sAcc + tid * 68 + q * 4);
                #pragma unroll
                for (int c = 0; c < 4; ++c) {
                    int j = q * 4 + c;
                    float v = silu_f(tt.f[c] + sbc[j]);
                    s0 += v * spW2[j * 3 + 0];
                    s1 += v * spW2[j * 3 + 1];
                    s2 += v * spW2[j * 3 + 2];
                }
            }
            int dn = sdst[tid];
            atomicAdd(&d_aggpm[dn * 3 + 0], sdv[tid * 3 + 0] * s0);
            atomicAdd(&d_aggpm[dn * 3 + 1], sdv[tid * 3 + 1] * s1);
            atomicAdd(&d_aggpm[dn * 3 + 2], sdv[tid * 3 + 2] * s2);
        }
    }
}

// ---------------- node (FFMA2, persistent) + h hi/lo emission ----------------
#define ND_SMEM ((64*132 + 64*68*5 + 192 + 256) * (int)sizeof(float))
__global__ void __launch_bounds__(256, 2)
node_kernel(const float* __restrict__ mW2, const float* __restrict__ mb2,
            const float* __restrict__ gamma, const float* __restrict__ beta,
            const float* __restrict__ uW1, const float* __restrict__ ub1,
            const float* __restrict__ uW2, const float* __restrict__ ub2,
            const float* __restrict__ uW3, const float* __restrict__ ub3,
            int ntiles, int l) {
    extern __shared__ float sm[];
    float* sfA  = sm;                    // 64*132
    float* sfB  = sfA + 64 * 132;        // 64*68
    float* sWm  = sfB + 64 * 68;
    float* sW1a = sWm + 64 * 68;
    float* sW2t = sW1a + 64 * 68;
    float* sW3t = sW2t + 64 * 68;
    float* sb1  = sW3t + 64 * 68;
    float* sb2  = sb1 + 64;
    float* sb3  = sb2 + 64;
    float* sAm  = sb3 + 64;
    float* sBm  = sAm + 64;
    float* sb2m = sBm + 64;
    float* sfnz = sb2m + 64;
    int tid = threadIdx.x;
    for (int idx = tid; idx < 64 * 64; idx += 256) {
        int k = idx >> 6, j = idx & 63;
        sWm[j * 68 + k]  = mW2[idx];
        sW1a[j * 68 + k] = uW1[idx];
        sW2t[j * 68 + k] = uW2[idx];
        sW3t[j * 68 + k] = uW3[idx];
    }
    if (tid < 64) {
        sb1[tid] = ub1[tid]; sb2[tid] = ub2[tid]; sb3[tid] = ub3[tid];
        float mu  = d_bnsum[l * 64 + tid]   * (1.0f / (float)EE);
        float var = d_bnsumsq[l * 64 + tid] * (1.0f / (float)EE) - mu * mu;
        float inv = rsqrtf(var + BN_EPS);
        float A = gamma[tid] * inv;
        sAm[tid] = A;
        sBm[tid] = beta[tid] - mu * A;
        sb2m[tid] = mb2[tid];
    }
    int et = tid & 15, jt = tid >> 4;

    for (int t = blockIdx.x; t < ntiles; t += gridDim.x) {
        int base = t * 64;
        __syncthreads();
        for (int idx = tid; idx < 64 * 16; idx += 256) {
            int e = idx >> 4, q = idx & 15;
            int n = base + e;
            float4 hv = make_float4(0.f, 0.f, 0.f, 0.f);
            F4U tt; tt.v = make_float4(0.f, 0.f, 0.f, 0.f);
            if (n < NN) {
                hv = *(const float4*)(d_h + n * 64 + q * 4);
                tt.v = *(const float4*)(d_summ1 + n * 64 + q * 4);
                *(float4*)(d_summ1 + n * 64 + q * 4) = make_float4(0.f, 0.f, 0.f, 0.f);
                float inv = d_invc[n];
                float f = (d_counts[n] > 0) ? 1.0f : 0.0f;
                #pragma unroll
                for (int c = 0; c < 4; ++c)
                    tt.f[c] = sAm[q * 4 + c] * (tt.f[c] * inv) + f * sBm[q * 4 + c];
            }
            *(float4*)(sfA + e * 132 + q * 4) = hv;
            *(float4*)(sfB + e * 68 + q * 4) = tt.v;
        }
        if (tid < 64) {
            int n = base + tid;
            float f = 0.0f;
            if (n < NN) {
                f = (d_counts[n] > 0) ? 1.0f : 0.0f;
                float inv = d_invc[n];
                #pragma unroll
                for (int c = 0; c < 3; ++c) {
                    d_pos[n * 3 + c] += d_aggpm[n * 3 + c] * inv;
                    d_aggpm[n * 3 + c] = 0.0f;
                }
            }
            sfnz[tid] = f;
        }
        __syncthreads();
        {   // agg = mnorm @ mW2 + f*mb2 -> sfA[:,64:128]
            ull a0[4][4] = {};
            gemm_acc4<68, 68>(sfB, sWm, 64, et, jt, a0);
            #pragma unroll
            for (int e = 0; e < 4; ++e) {
                int er = et + 16 * e;
                float f = sfnz[er];
                F4U o;
                #pragma unroll
                for (int j = 0; j < 4; ++j)
                    o.f[j] = lane_sum(a0[e][j]) + f * sb2m[jt * 4 + j];
                *(float4*)(sfA + er * 132 + 64 + jt * 4) = o.v;
            }
        }
        __syncthreads();
        ull a1[4][4] = {};
        gemm_acc4<132, 68>(sfA, sW1a, 64, et, jt, a1);
        {   // uW1 rows 64..127 direct from gmem (L2-hot broadcast)
            const float* fb = sfA + et * 132 + 64;
            #pragma unroll 2
            for (int k0 = 0; k0 < 64; k0 += 4) {
                ull ww[4][2];
                #pragma unroll
                for (int j = 0; j < 4; ++j) {
                    F4U tw;
                    tw.f[0] = uW1[(64 + k0 + 0) * 64 + jt * 4 + j];
                    tw.f[1] = uW1[(64 + k0 + 1) * 64 + jt * 4 + j];
                    tw.f[2] = uW1[(64 + k0 + 2) * 64 + jt * 4 + j];
                    tw.f[3] = uW1[(64 + k0 + 3) * 64 + jt * 4 + j];
                    ww[j][0] = tw.u[0]; ww[j][1] = tw.u[1];
                }
                #pragma unroll
                for (int e = 0; e < 4; ++e) {
                    F4U tf; tf.v = *(const float4*)(fb + e * 16 * 132 + k0);
                    #pragma unroll
                    for (int j = 0; j < 4; ++j) {
                        a1[e][j] = ffma2(tf.u[0], ww[j][0], a1[e][j]);
                        a1[e][j] = ffma2(tf.u[1], ww[j][1], a1[e][j]);
                    }
                }
            }
        }
        __syncthreads();
        #pragma unroll
        for (int e = 0; e < 4; ++e) {
            F4U o;
            #pragma unroll
            for (int j = 0; j < 4; ++j)
                o.f[j] = silu_f(lane_sum(a1[e][j]) + sb1[jt * 4 + j]);
            *(float4*)(sfB + (et + 16 * e) * 68 + jt * 4) = o.v;
        }
        __syncthreads();
        {
            ull a2[4][4] = {};
            gemm_acc4<68, 68>(sfB, sW2t, 64, et, jt, a2);
            #pragma unroll
            for (int e = 0; e < 4; ++e) {
                F4U o;
                #pragma unroll
                for (int j = 0; j < 4; ++j)
                    o.f[j] = silu_f(lane_sum(a2[e][j]) + sb2[jt * 4 + j]);
                *(float4*)(sfA + (et + 16 * e) * 132 + jt * 4) = o.v;
            }
        }
        __syncthreads();
        {
            ull a3[4][4] = {};
            gemm_acc4<132, 68>(sfA, sW3t, 64, et, jt, a3);
            #pragma unroll
            for (int e = 0; e < 4; ++e) {
                int n = base + et + 16 * e;
                if (n < NN) {
                    F4U h; h.v = *(const float4*)(d_h + n * 64 + jt * 4);
                    F4U o;
                    #pragma unroll
                    for (int j = 0; j < 4; ++j)
                        o.f[j] = h.f[j] + lane_sum(a3[e][j]) + sb3[jt * 4 + j];
                    *(float4*)(d_h + n * 64 + jt * 4) = o.v;
                    __nv_bfloat16 hb[4]; float lo[4];
                    #pragma unroll
                    for (int j = 0; j < 4; ++j) {
                        hb[j] = __float2bfloat16(o.f[j]);
                        lo[j] = o.f[j] - __bfloat162float(hb[j]);
                    }
                    uint2 H, L;
                    H.x = pack_bf(hb[0], hb[1]); H.y = pack_bf(hb[2], hb[3]);
                    L.x = pack_bf(__float2bfloat16(lo[0]), __float2bfloat16(lo[1]));
                    L.y = pack_bf(__float2bfloat16(lo[2]), __float2bfloat16(lo[3]));
                    *(uint2*)(d_hhi + n * 64 + jt * 4) = H;
                    *(uint2*)(d_hlo + n * 64 + jt * 4) = L;
                }
            }
        }
    }
}

// ---------------- energy MLP ----------------
#define EN_SMEM ((64*68*2 + 64*68*2 + 64 + 64 + 64 + 4) * (int)sizeof(float))
__global__ void energy_kernel(const float* __restrict__ W1, const float* __restrict__ b1,
                              const float* __restrict__ W2, const float* __restrict__ b2,
                              const float* __restrict__ W3, const float* __restrict__ b3,
                              float* __restrict__ out) {
    extern __shared__ float sm[];
    float* sfA  = sm;
    float* sfB  = sfA + 64 * 68;
    float* sW1t = sfB + 64 * 68;
    float* sW2t = sW1t + 64 * 68;
    float* sW3  = sW2t + 64 * 68;
    float* sb1  = sW3 + 64;
    float* sb2  = sb1 + 64;
    float* sb3  = sb2 + 64;
    int tid = threadIdx.x;
    int base = blockIdx.x * 64;
    for (int idx = tid; idx < 64 * 64; idx += 256) {
        int k = idx >> 6, j = idx & 63;
        sW1t[j * 68 + k] = W1[idx];
        sW2t[j * 68 + k] = W2[idx];
    }
    if (tid < 64) { sW3[tid] = W3[tid]; sb1[tid] = b1[tid]; sb2[tid] = b2[tid]; }
    if (tid == 0) sb3[0] = b3[0];
    for (int idx = tid; idx < 64 * 16; idx += 256) {
        int e = idx >> 4, q = idx & 15;
        int n = base + e;
        float4 v = (n < NN) ? *(const float4*)(d_h + n * 64 + q * 4)
                            : make_float4(0.f, 0.f, 0.f, 0.f);
        *(float4*)(sfA + e * 68 + q * 4) = v;
    }
    __syncthreads();
    int et = tid & 15, jt = tid >> 4;
    {
        ull acc[4][4] = {};
        gemm_acc4<68, 68>(sfA, sW1t, 64, et, jt, acc);
        #pragma unroll
        for (int e = 0; e < 4; ++e) {
            F4U o;
            #pragma unroll
            for (int j = 0; j < 4; ++j)
                o.f[j] = silu_f(lane_sum(acc[e][j]) + sb1[jt * 4 + j]);
            *(float4*)(sfB + (et + 16 * e) * 68 + jt * 4) = o.v;
        }
    }
    __syncthreads();
    {
        ull acc[4][4] = {};
        gemm_acc4<68, 68>(sfB, sW2t, 64, et, jt, acc);
        #pragma unroll
        for (int e = 0; e < 4; ++e) {
            F4U o;
            #pragma unroll
            for (int j = 0; j < 4; ++j)
                o.f[j] = silu_f(lane_sum(acc[e][j]) + sb2[jt * 4 + j]);
            *(float4*)(sfA + (et + 16 * e) * 68 + jt * 4) = o.v;
        }
    }
    __syncthreads();
    if (tid < 64) {
        int n = base + tid;
        if (n < NN) {
            float s = sb3[0];
            #pragma unroll
            for (int q = 0; q < 16; ++q) {
                F4U t; t.v = *(const float4*)(sfA + tid * 68 + q * 4);
                #pragma unroll
                for (int c = 0; c < 4; ++c) s += t.f[c] * sW3[q * 4 + c];
            }
            out[n] = s;
        }
    }
}

// ---------------- launch ----------------
extern "C" void kernel_launch(void* const* d_in, const int* in_sizes, int n_in,
                              void* d_out, int out_size) {
    const float* h_in   = (const float*)d_in[0];
    const float* pos    = (const float*)d_in[1];
    const float* cell   = (const float*)d_in[2];
    const int*   esrc   = (const int*)d_in[3];
    const int*   edst   = (const int*)d_in[4];
    const float* emb_W1 = (const float*)d_in[5];
    const float* emb_b1 = (const float*)d_in[6];
    const float* emb_W2 = (const float*)d_in[7];
    const float* emb_b2 = (const float*)d_in[8];
    const float* msg_W1 = (const float*)d_in[9];
    const float* msg_b1 = (const float*)d_in[10];
    const float* bn_g   = (const float*)d_in[11];
    const float* bn_b   = (const float*)d_in[12];
    const float* msg_W2 = (const float*)d_in[13];
    const float* msg_b2 = (const float*)d_in[14];
    const float* upd_W1 = (const float*)d_in[15];
    const float* upd_b1 = (const float*)d_in[16];
    const float* upd_W2 = (const float*)d_in[17];
    const float* upd_b2 = (const float*)d_in[18];
    const float* upd_W3 = (const float*)d_in[19];
    const float* upd_b3 = (const float*)d_in[20];
    const float* pos_W1 = (const float*)d_in[21];
    const float* pos_b1 = (const float*)d_in[22];
    const float* pos_W2 = (const float*)d_in[23];
    const float* pos_b2 = (const float*)d_in[24];
    const float* en_W1  = (const float*)d_in[25];
    const float* en_b1  = (const float*)d_in[26];
    const float* en_W2  = (const float*)d_in[27];
    const float* en_b2  = (const float*)d_in[28];
    const float* en_W3  = (const float*)d_in[29];
    const float* en_b3  = (const float*)d_in[30];
    float* out = (float*)d_out;

    static int attr_done = 0;
    if (!attr_done) {
        cudaFuncSetAttribute(embed_kernel,  cudaFuncAttributeMaxDynamicSharedMemorySize, EM_SMEM);
        cudaFuncSetAttribute(pass1_wmma,    cudaFuncAttributeMaxDynamicSharedMemorySize, P1_SMEM);
        cudaFuncSetAttribute(pass2_wmma,    cudaFuncAttributeMaxDynamicSharedMemorySize, P2_SMEM);
        cudaFuncSetAttribute(node_kernel,   cudaFuncAttributeMaxDynamicSharedMemorySize, ND_SMEM);
        cudaFuncSetAttribute(energy_kernel, cudaFuncAttributeMaxDynamicSharedMemorySize, EN_SMEM);
        attr_done = 1;
    }

    const int P1_GRID = 148 * 2;
    const int P2_GRID = 148 * 2;
    const int ND_TILES = (NN + 63) / 64;
    const int ND_GRID = 148 * 2;

    init_kernel<<<(NN * F + 255) / 256, 256>>>(pos);
    count_kernel<<<(EE + 255) / 256, 256>>>(edst);
    inv_kernel<<<(NN + 255) / 256, 256>>>();
    wconv_kernel<<<(NL * F * 128 + 255) / 256, 256>>>(msg_W1);
    embed_kernel<<<313, 256, EM_SMEM>>>(h_in, emb_W1, emb_b1, emb_W2, emb_b2);

    for (int l = 0; l < NL; ++l) {
        pass1_wmma<<<P1_GRID, 256, P1_SMEM>>>(esrc, edst, cell,
                                              msg_W1 + l * (2 * F + 1) * F, msg_b1 + l * F, l);
        pass2_wmma<<<P2_GRID, 256, P2_SMEM>>>(edst,
                                              bn_g + l * F, bn_b + l * F,
                                              msg_W2 + l * F * F, msg_b2 + l * F,
                                              pos_W1 + l * F * F, pos_b1 + l * F,
                                              pos_W2 + l * F * DIM, pos_b2 + l * DIM, l);
        node_kernel<<<ND_GRID, 256, ND_SMEM>>>(msg_W2 + l * F * F, msg_b2 + l * F,
                                               bn_g + l * F, bn_b + l * F,
                                               upd_W1 + l * 2 * F * F, upd_b1 + l * F,
                                               upd_W2 + l * F * F, upd_b2 + l * F,
                                               upd_W3 + l * F * F, upd_b3 + l * F,
                                               ND_TILES, l);
    }
    energy_kernel<<<313, 256, EN_SMEM>>>(en_W1, en_b1, en_W2, en_b2, en_W3, en_b3, out);
}